// round 3
// baseline (speedup 1.0000x reference)
#include <cuda_runtime.h>

#define B_  512
#define T_  2048
#define I_  33
#define H_  64
#define O_  2
#define BT_ (B_ * T_)

// Packed fp32x2 FMA (Blackwell FFMA2) — only reachable via PTX fma.rn.f32x2.
__device__ __forceinline__ void ffma2(float2& d, float2 a, float2 b) {
    asm("fma.rn.f32x2 %0, %1, %2, %0;"
        : "+l"(*reinterpret_cast<unsigned long long*>(&d))
        : "l"(*reinterpret_cast<const unsigned long long*>(&a)),
          "l"(*reinterpret_cast<const unsigned long long*>(&b)));
}

__device__ __forceinline__ float fast_tanh(float x) {
    float ax = fabsf(x);
    float e  = __expf(-2.0f * ax);
    float r  = __fdividef(1.0f - e, 1.0f + e);
    return copysignf(r, x);
}

// ---------------- Phase 1: xW = x @ W_ih^T + b_ih  (written into hidden region) ----------------
__global__ __launch_bounds__(128) void xw_kernel(
    const float* __restrict__ x, const float* __restrict__ W_ih,
    const float* __restrict__ b_ih, float* __restrict__ xw)
{
    __shared__ float Wc[I_ * H_];              // col-major: Wc[i*64 + j] = W_ih[j][i]
    __shared__ float bsh[H_];
    __shared__ __align__(16) float xs[128 * I_];

    int tid = threadIdx.x;
    for (int e = tid; e < I_ * H_; e += 128) {
        int i = e >> 6, j = e & 63;
        Wc[e] = W_ih[j * I_ + i];
    }
    if (tid < H_) bsh[tid] = b_ih[tid];

    // Cooperative, coalesced x staging: 128 rows * 33 floats = 1056 float4, contiguous + 16B aligned.
    const float4* xg = (const float4*)(x + (size_t)blockIdx.x * 128 * I_);
    float4* xs4 = (float4*)xs;
    #pragma unroll
    for (int q = 0; q < 9; ++q) {
        int idx = tid + q * 128;
        if (idx < (128 * I_) / 4) xs4[idx] = xg[idx];
    }
    __syncthreads();

    // Preload the full x row into registers: 33 independent LDS, batched -> MLP-deep,
    // removes the per-iteration LDS from the FFMA dependence chain.
    float xv[I_];
    const float* xr = xs + tid * I_;           // stride 33 floats -> conflict-free (33 odd)
    #pragma unroll
    for (int i = 0; i < I_; ++i) xv[i] = xr[i];

    float2 acc[32];
    const float2* b2 = (const float2*)bsh;
    #pragma unroll
    for (int q = 0; q < 32; ++q) acc[q] = b2[q];

    #pragma unroll 3
    for (int i = 0; i < I_; ++i) {
        float2 xi2 = make_float2(xv[i], xv[i]);
        const float4* wr = (const float4*)(Wc + i * H_);   // lane-uniform -> smem broadcast
        #pragma unroll
        for (int q = 0; q < 16; ++q) {
            float4 w = wr[q];
            ffma2(acc[2 * q],     make_float2(w.x, w.y), xi2);
            ffma2(acc[2 * q + 1], make_float2(w.z, w.w), xi2);
        }
    }

    size_t r = (size_t)blockIdx.x * 128 + tid;
    float4* op = (float4*)(xw + r * H_);
    #pragma unroll
    for (int q = 0; q < 16; ++q)
        op[q] = make_float4(acc[2 * q].x, acc[2 * q].y, acc[2 * q + 1].x, acc[2 * q + 1].y);
}

// ---------------- Phase 2: sequential recurrence, 2 warps per batch row ----------------
// Row split: warp-pair (2p, 2p+1); lane l of half h computes output j = h*32 + l.
// Per-warp issue: 32 FFMA2 (64 cyc), two 16-deep chains (64 cyc latency) — overlapped.
// Cross-warp sync: named barrier per pair (drains STS); double-buffered h kills the race.
__global__ __launch_bounds__(256, 1) void rnn_kernel(
    float* __restrict__ hs, const float* __restrict__ h0,
    const float* __restrict__ W_hh, const float* __restrict__ b_hh)
{
    __shared__ __align__(16) float hb[4][2][H_];
    int wid  = threadIdx.x >> 5;
    int l    = threadIdx.x & 31;
    int pair = wid >> 1;
    int half = wid & 1;
    int row  = blockIdx.x * 4 + pair;
    int j    = half * 32 + l;

    // W_hh row j register-resident as 32 k-pairs (64 regs).
    float2 w[32];
    const float4* wr = (const float4*)(W_hh + j * H_);
    #pragma unroll
    for (int q = 0; q < 16; ++q) {
        float4 a = wr[q];
        w[2 * q]     = make_float2(a.x, a.y);
        w[2 * q + 1] = make_float2(a.z, a.w);
    }
    float bj = b_hh[j];

    hb[pair][0][j] = h0[row * H_ + j];

    float* base = hs + (size_t)row * T_ * H_;
    // prefetch depth 4 against DRAM latency (~577 cyc > 2 steps); bias folded in.
    float xp[4];
    #pragma unroll
    for (int k = 0; k < 4; ++k) xp[k] = base[k * H_ + j] + bj;

    __syncthreads();

    int barid = pair + 1;                      // named barriers 1..4, 64 threads each
    for (int t = 0; t < T_; t += 4) {
        #pragma unroll
        for (int k = 0; k < 4; ++k) {
            int tt = t + k;
            const float4* hr = (const float4*)hb[pair][tt & 1];       // lane-uniform LDS.128 broadcast
            float*        hw = hb[pair][(tt + 1) & 1];
            float2 a0 = make_float2(xp[k], 0.f);                      // x+b seeded into chain 0
            float2 a1 = make_float2(0.f, 0.f);
            #pragma unroll
            for (int q = 0; q < 16; ++q) {
                float4 h4 = hr[q];
                ffma2(a0, w[2 * q],     make_float2(h4.x, h4.y));
                ffma2(a1, w[2 * q + 1], make_float2(h4.z, h4.w));
            }
            float hn = fast_tanh((a0.x + a0.y) + (a1.x + a1.y));
            hw[j] = hn;                                               // smem ping-pong for next step
            base[(size_t)tt * H_ + j] = hn;                           // overwrite xW slot with h (off path)
            int tn = tt + 4; if (tn > T_ - 1) tn = T_ - 1;            // prefetch t+4 (never overwritten yet)
            xp[k] = base[(size_t)tn * H_ + j] + bj;
            asm volatile("bar.sync %0, 64;" :: "r"(barid) : "memory");
        }
    }
}

// ---------------- Phase 3: predictions = hs @ W_ro^T + b_ro ----------------
__global__ __launch_bounds__(256) void pred_kernel(
    const float* __restrict__ hs, const float* __restrict__ W_ro,
    const float* __restrict__ b_ro, float* __restrict__ pred)
{
    __shared__ float w0[H_], w1[H_];
    int tid = threadIdx.x;
    if (tid < H_) { w0[tid] = W_ro[tid]; w1[tid] = W_ro[H_ + tid]; }
    __syncthreads();

    size_t r = (size_t)blockIdx.x * 256 + tid;
    const float4* hp = (const float4*)(hs + r * H_);
    float p0a = 0.f, p0b = 0.f, p1a = 0.f, p1b = 0.f;
    #pragma unroll
    for (int q = 0; q < 16; ++q) {
        float4 h = hp[q];
        p0a += h.x * w0[4 * q]     + h.z * w0[4 * q + 2];
        p0b += h.y * w0[4 * q + 1] + h.w * w0[4 * q + 3];
        p1a += h.x * w1[4 * q]     + h.z * w1[4 * q + 2];
        p1b += h.y * w1[4 * q + 1] + h.w * w1[4 * q + 3];
    }
    ((float2*)pred)[r] = make_float2(p0a + p0b + b_ro[0], p1a + p1b + b_ro[1]);
}

extern "C" void kernel_launch(void* const* d_in, const int* in_sizes, int n_in,
                              void* d_out, int out_size)
{
    const float* x   = (const float*)d_in[0];
    const float* h0  = (const float*)d_in[1];
    const float* Wih = (const float*)d_in[2];
    const float* Whh = (const float*)d_in[3];
    const float* bih = (const float*)d_in[4];
    const float* bhh = (const float*)d_in[5];
    const float* Wro = (const float*)d_in[6];
    const float* bro = (const float*)d_in[7];

    float* out  = (float*)d_out;
    float* pred = out;                               // [B,T,O]
    float* hsb  = out + (size_t)B_ * T_ * O_;        // [B,T,H] — staged as xW, overwritten with h

    xw_kernel  <<<BT_ / 128, 128>>>(x, Wih, bih, hsb);
    rnn_kernel <<<B_ / 4,    256>>>(hsb, h0, Whh, bhh);
    pred_kernel<<<BT_ / 256, 256>>>(hsb, Wro, bro, pred);
}

// round 5
// speedup vs baseline: 1.5212x; 1.5212x over previous
#include <cuda_runtime.h>

#define B_  512
#define T_  2048
#define I_  33
#define H_  64
#define O_  2
#define BT_ (B_ * T_)

// Packed fp32x2 ops (Blackwell) — only reachable via PTX.
__device__ __forceinline__ void ffma2(float2& d, float2 a, float2 b) {
    asm("fma.rn.f32x2 %0, %1, %2, %0;"
        : "+l"(*reinterpret_cast<unsigned long long*>(&d))
        : "l"(*reinterpret_cast<const unsigned long long*>(&a)),
          "l"(*reinterpret_cast<const unsigned long long*>(&b)));
}
__device__ __forceinline__ float2 fadd2(float2 a, float2 b) {
    float2 r;
    asm("add.rn.f32x2 %0, %1, %2;"
        : "=l"(*reinterpret_cast<unsigned long long*>(&r))
        : "l"(*reinterpret_cast<const unsigned long long*>(&a)),
          "l"(*reinterpret_cast<const unsigned long long*>(&b)));
    return r;
}
__device__ __forceinline__ float ex2a(float x) {
    float y; asm("ex2.approx.f32 %0, %1;" : "=f"(y) : "f"(x)); return y;
}
__device__ __forceinline__ float rcpa(float x) {
    float y; asm("rcp.approx.f32 %0, %1;" : "=f"(y) : "f"(x)); return y;
}
// tanh(x) = sign(x) * (1-e)/(1+e), e = 2^(-2x/ln2 * |x|)
__device__ __forceinline__ float fast_tanh(float x) {
    float ax = fabsf(x);
    float e  = ex2a(-2.8853900817779268f * ax);
    float r  = (1.0f - e) * rcpa(1.0f + e);
    return copysignf(r, x);
}

// ---------------- Phase 1: xW = x @ W_ih^T + b_ih  (into hidden region) ----------------
// 2 threads per row (32 outputs each) -> ~half the regs of R1, ~2x occupancy.
__global__ __launch_bounds__(256) void xw_kernel(
    const float* __restrict__ x, const float* __restrict__ W_ih,
    const float* __restrict__ b_ih, float* __restrict__ xw)
{
    __shared__ float Wc[I_ * H_];              // col-major: Wc[i*64 + j] = W_ih[j][i]
    __shared__ float bsh[H_];
    __shared__ __align__(16) float xs[128 * I_];

    int tid  = threadIdx.x;
    int rl   = tid & 127;                      // local row
    int j0   = (tid >> 7) * 32;                // output half (warp-uniform)

    for (int e = tid; e < I_ * H_; e += 256) {
        int i = e >> 6, j = e & 63;
        Wc[e] = W_ih[j * I_ + i];
    }
    if (tid < H_) bsh[tid] = b_ih[tid];

    // Coalesced x staging: 128 rows * 33 floats = 1056 float4.
    const float4* xg = (const float4*)(x + (size_t)blockIdx.x * 128 * I_);
    float4* xs4 = (float4*)xs;
    #pragma unroll
    for (int q = 0; q < 5; ++q) {
        int idx = tid + q * 256;
        if (idx < (128 * I_) / 4) xs4[idx] = xg[idx];
    }
    __syncthreads();

    float2 acc[16];
    const float2* b2 = (const float2*)(bsh + j0);
    #pragma unroll
    for (int q = 0; q < 16; ++q) acc[q] = b2[q];

    const float* xr = xs + rl * I_;            // stride 33 -> conflict-free
    #pragma unroll
    for (int i = 0; i < I_; ++i) {
        float xi = xr[i];
        float2 xi2 = make_float2(xi, xi);
        const float4* wr = (const float4*)(Wc + i * H_ + j0);  // warp-uniform -> broadcast
        #pragma unroll
        for (int q = 0; q < 8; ++q) {
            float4 w = wr[q];
            ffma2(acc[2 * q],     make_float2(w.x, w.y), xi2);
            ffma2(acc[2 * q + 1], make_float2(w.z, w.w), xi2);
        }
    }

    size_t r = (size_t)blockIdx.x * 128 + rl;
    float4* op = (float4*)(xw + r * H_ + j0);
    #pragma unroll
    for (int q = 0; q < 8; ++q)
        op[q] = make_float4(acc[2 * q].x, acc[2 * q].y, acc[2 * q + 1].x, acc[2 * q + 1].y);
}

// ---------------- Phase 2: sequential recurrence, 1 warp per batch row ----------------
// Intra-warp only (R3 proved: no barriers on the serial path). Lane l computes
// h[l] and h[l+32]; W_hh rows register-resident; 4 chains/output (depth 8);
// ping-pong smem h + one __syncwarp per step; lean tanh.
__global__ __launch_bounds__(128, 1) void rnn_kernel(
    float* __restrict__ hs, const float* __restrict__ h0,
    const float* __restrict__ W_hh, const float* __restrict__ b_hh)
{
    __shared__ __align__(16) float hb[4][2][H_];
    int w = threadIdx.x >> 5;
    int l = threadIdx.x & 31;
    int row = blockIdx.x * 4 + w;

    // W_hh rows l and l+32 as 32 k-pairs each (128 regs).
    float2 wA[32], wB[32];
    const float4* wra = (const float4*)(W_hh + l * H_);
    const float4* wrb = (const float4*)(W_hh + (l + 32) * H_);
    #pragma unroll
    for (int q = 0; q < 16; ++q) {
        float4 a = wra[q];
        wA[2 * q] = make_float2(a.x, a.y); wA[2 * q + 1] = make_float2(a.z, a.w);
        float4 b = wrb[q];
        wB[2 * q] = make_float2(b.x, b.y); wB[2 * q + 1] = make_float2(b.z, b.w);
    }
    float bA = b_hh[l], bB = b_hh[l + 32];

    hb[w][0][l]      = h0[row * H_ + l];
    hb[w][0][l + 32] = h0[row * H_ + l + 32];

    float* base = hs + (size_t)row * T_ * H_;
    // prefetch depth 4 vs DRAM latency; bias folded in at load.
    float xA[4], xB[4];
    #pragma unroll
    for (int k = 0; k < 4; ++k) {
        xA[k] = base[k * H_ + l]      + bA;
        xB[k] = base[k * H_ + l + 32] + bB;
    }
    __syncwarp();

    for (int t = 0; t < T_; t += 4) {
        #pragma unroll
        for (int k = 0; k < 4; ++k) {
            int tt = t + k;
            const float4* hr = (const float4*)hb[w][tt & 1];       // uniform LDS.128 broadcast
            float*        hw = hb[w][(tt + 1) & 1];

            // 4 chains per output, depth 8 each.
            float2 a0 = make_float2(xA[k], 0.f), a1 = make_float2(0.f, 0.f);
            float2 a2 = make_float2(0.f, 0.f),   a3 = make_float2(0.f, 0.f);
            float2 c0 = make_float2(xB[k], 0.f), c1 = make_float2(0.f, 0.f);
            float2 c2 = make_float2(0.f, 0.f),   c3 = make_float2(0.f, 0.f);
            #pragma unroll
            for (int q = 0; q < 8; ++q) {
                float4 h4a = hr[2 * q];
                float4 h4b = hr[2 * q + 1];
                float2 p0 = make_float2(h4a.x, h4a.y);
                float2 p1 = make_float2(h4a.z, h4a.w);
                float2 p2 = make_float2(h4b.x, h4b.y);
                float2 p3 = make_float2(h4b.z, h4b.w);
                ffma2(a0, wA[4 * q],     p0);
                ffma2(a1, wA[4 * q + 1], p1);
                ffma2(a2, wA[4 * q + 2], p2);
                ffma2(a3, wA[4 * q + 3], p3);
                ffma2(c0, wB[4 * q],     p0);
                ffma2(c1, wB[4 * q + 1], p1);
                ffma2(c2, wB[4 * q + 2], p2);
                ffma2(c3, wB[4 * q + 3], p3);
            }
            float2 sA = fadd2(fadd2(a0, a1), fadd2(a2, a3));
            float2 sB = fadd2(fadd2(c0, c1), fadd2(c2, c3));
            float hA = fast_tanh(sA.x + sA.y);
            float hB = fast_tanh(sB.x + sB.y);

            hw[l]      = hA;  hw[l + 32] = hB;                      // smem for next step
            base[(size_t)tt * H_ + l]      = hA;                    // output write (off path)
            base[(size_t)tt * H_ + l + 32] = hB;

            int tn = tt + 4; if (tn > T_ - 1) tn = T_ - 1;          // prefetch (region still xW)
            xA[k] = base[(size_t)tn * H_ + l]      + bA;
            xB[k] = base[(size_t)tn * H_ + l + 32] + bB;
            __syncwarp();
        }
    }
}

// ---------------- Phase 3: predictions = hs @ W_ro^T + b_ro ----------------
__global__ __launch_bounds__(256) void pred_kernel(
    const float* __restrict__ hs, const float* __restrict__ W_ro,
    const float* __restrict__ b_ro, float* __restrict__ pred)
{
    __shared__ float w0[H_], w1[H_];
    int tid = threadIdx.x;
    if (tid < H_) { w0[tid] = W_ro[tid]; w1[tid] = W_ro[H_ + tid]; }
    __syncthreads();

    size_t r = (size_t)blockIdx.x * 256 + tid;
    const float4* hp = (const float4*)(hs + r * H_);
    float p0a = 0.f, p0b = 0.f, p1a = 0.f, p1b = 0.f;
    #pragma unroll
    for (int q = 0; q < 16; ++q) {
        float4 h = hp[q];
        p0a += h.x * w0[4 * q]     + h.z * w0[4 * q + 2];
        p0b += h.y * w0[4 * q + 1] + h.w * w0[4 * q + 3];
        p1a += h.x * w1[4 * q]     + h.z * w1[4 * q + 2];
        p1b += h.y * w1[4 * q + 1] + h.w * w1[4 * q + 3];
    }
    ((float2*)pred)[r] = make_float2(p0a + p0b + b_ro[0], p1a + p1b + b_ro[1]);
}

extern "C" void kernel_launch(void* const* d_in, const int* in_sizes, int n_in,
                              void* d_out, int out_size)
{
    const float* x   = (const float*)d_in[0];
    const float* h0  = (const float*)d_in[1];
    const float* Wih = (const float*)d_in[2];
    const float* Whh = (const float*)d_in[3];
    const float* bih = (const float*)d_in[4];
    const float* bhh = (const float*)d_in[5];
    const float* Wro = (const float*)d_in[6];
    const float* bro = (const float*)d_in[7];

    float* out  = (float*)d_out;
    float* pred = out;                               // [B,T,O]
    float* hsb  = out + (size_t)B_ * T_ * O_;        // [B,T,H] — staged xW, overwritten with h

    xw_kernel  <<<BT_ / 128, 256>>>(x, Wih, bih, hsb);
    rnn_kernel <<<B_ / 4,    128>>>(hsb, h0, Whh, bhh);
    pred_kernel<<<BT_ / 256, 256>>>(hsb, Wro, bro, pred);
}